// round 2
// baseline (speedup 1.0000x reference)
#include <cuda_runtime.h>
#include <math.h>

#define NN 50000
#define EE 800000
#define EPD 850000   // E + N self loops
#define HH 8
#define CC 16
#define HC 128       // H*C

// ---------------- scratch (device globals; no allocation allowed) ----------------
__device__ __align__(16) float g_h1[(size_t)NN * HC];
__device__ __align__(16) float g_hA[(size_t)NN * HC];
__device__ __align__(16) float g_hB[(size_t)NN * HC];
__device__ __align__(16) float g_z [(size_t)NN * HC];
__device__ __align__(16) float g_zs[(size_t)NN * HC];
__device__ __align__(16) float g_ae[(size_t)EPD * HH];
__device__ float g_deg [(size_t)NN * HH];
__device__ float g_dinv[(size_t)NN * HH];

__device__ __forceinline__ float eluf(float x) { return x > 0.f ? x : expm1f(x); }
__device__ __forceinline__ float softplusf(float x) {
    return x > 0.f ? x + log1pf(expf(-x)) : log1pf(expf(x));
}

// ---------------- GEMM: C[N,128] = (A[N,KDIM] @ W[KDIM,128]) + b, optional ELU ----
// BM=64, BN=128, BK=16, 256 threads, thread tile 8x4.
// SRC: 0 -> use A arg, 1 -> use g_h1.  DST: 0 -> g_h1, 1 -> g_hA.
template<int KDIM, bool ELU_OUT, int SRC, int DST>
__global__ void gemm_k(const float* __restrict__ Aarg, const float* __restrict__ W,
                       const float* __restrict__ bias)
{
    const float* A  = (SRC == 0) ? Aarg : g_h1;
    float* Cout     = (DST == 0) ? g_h1 : g_hA;
    __shared__ float As[16][65];
    __shared__ float Bs[16][128];
    const int tid = threadIdx.x;
    const int block_row = blockIdx.x * 64;
    const int row_t = tid >> 5;   // 0..7
    const int col_t = tid & 31;   // 0..31

    float acc[8][4];
    #pragma unroll
    for (int j = 0; j < 8; j++) { acc[j][0]=acc[j][1]=acc[j][2]=acc[j][3]=0.f; }

    for (int k0 = 0; k0 < KDIM; k0 += 16) {
        // A tile 64x16
        {
            int r  = tid >> 2;
            int kk = (tid & 3) << 2;
            int grow = block_row + r;
            float4 v = make_float4(0.f,0.f,0.f,0.f);
            if (grow < NN) v = *(const float4*)&A[(size_t)grow * KDIM + k0 + kk];
            As[kk+0][r] = v.x; As[kk+1][r] = v.y; As[kk+2][r] = v.z; As[kk+3][r] = v.w;
        }
        // B tile 16x128
        #pragma unroll
        for (int i = 0; i < 2; i++) {
            int idx = tid + (i << 8);
            int bk  = idx >> 5;
            int cc  = (idx & 31) << 2;
            *(float4*)&Bs[bk][cc] = *(const float4*)&W[(size_t)(k0 + bk) * HC + cc];
        }
        __syncthreads();
        #pragma unroll
        for (int k = 0; k < 16; k++) {
            float4 b4 = *(float4*)&Bs[k][col_t << 2];
            #pragma unroll
            for (int j = 0; j < 8; j++) {
                float a = As[k][(row_t << 3) + j];
                acc[j][0] = fmaf(a, b4.x, acc[j][0]);
                acc[j][1] = fmaf(a, b4.y, acc[j][1]);
                acc[j][2] = fmaf(a, b4.z, acc[j][2]);
                acc[j][3] = fmaf(a, b4.w, acc[j][3]);
            }
        }
        __syncthreads();
    }
    float4 bb = *(const float4*)&bias[col_t << 2];
    #pragma unroll
    for (int j = 0; j < 8; j++) {
        int grow = block_row + (row_t << 3) + j;
        if (grow < NN) {
            float4 o;
            o.x = acc[j][0] + bb.x; o.y = acc[j][1] + bb.y;
            o.z = acc[j][2] + bb.z; o.w = acc[j][3] + bb.w;
            if (ELU_OUT) { o.x = eluf(o.x); o.y = eluf(o.y); o.z = eluf(o.z); o.w = eluf(o.w); }
            *(float4*)&Cout[(size_t)grow * HC + (col_t << 2)] = o;
        }
    }
}

// ---------------- hop-0: g = <hop_att0, elu(h)> + bias0 ; z = h*g ; zs = z*decay0 --
__global__ void hop0_kernel(const float* __restrict__ hop_att0,
                            const float* __restrict__ hop_bias0, float decay0)
{
    int w = (blockIdx.x * blockDim.x + threadIdx.x) >> 5;
    int lane = threadIdx.x & 31;
    if (w >= NN) return;
    int head = lane >> 2, sub = lane & 3;
    size_t off = (size_t)w * HC + (lane << 2);
    float4 h4 = *(const float4*)&g_hA[off];
    const float* av = hop_att0 + head * CC + (sub << 2);
    float p = eluf(h4.x)*av[0] + eluf(h4.y)*av[1] + eluf(h4.z)*av[2] + eluf(h4.w)*av[3];
    p += __shfl_xor_sync(0xffffffffu, p, 1);
    p += __shfl_xor_sync(0xffffffffu, p, 2);
    float g = p + hop_bias0[head];
    float4 z4 = make_float4(h4.x*g, h4.y*g, h4.z*g, h4.w*g);
    *(float4*)&g_z[off] = z4;
    float4 zs4 = make_float4(z4.x*decay0, z4.y*decay0, z4.z*decay0, z4.w*decay0);
    *(float4*)&g_zs[off] = zs4;
}

// ---------------- per-hop zero of h_new and deg -----------------------------------
__global__ void zero_kernel(int flip)  // flip=1 -> new is g_hB, flip=0 -> new is g_hA
{
    float* hnew = flip ? g_hB : g_hA;
    int i = blockIdx.x * blockDim.x + threadIdx.x;
    int stride = gridDim.x * blockDim.x;
    for (int j = i; j < NN * HC; j += stride) hnew[j] = 0.f;
    for (int j = i; j < NN * HH; j += stride) g_deg[j] = 0.f;
}

// ---------------- edge attention: a = softplus(<atts, elu(zs_i+zs_j)>)+1e-6 -------
__global__ void edge_att_kernel(const int* __restrict__ ei,
                                const float* __restrict__ atts_k)
{
    int e = (blockIdx.x * blockDim.x + threadIdx.x) >> 5;
    int lane = threadIdx.x & 31;
    if (e >= EPD) return;
    int r, c;
    if (e < EE) { r = ei[e]; c = ei[EE + e]; }
    else        { r = c = e - EE; }
    int head = lane >> 2, sub = lane & 3;
    float4 zi = *(const float4*)&g_zs[(size_t)c * HC + (lane << 2)];
    float4 zj = *(const float4*)&g_zs[(size_t)r * HC + (lane << 2)];
    const float* av = atts_k + head * CC + (sub << 2);
    float p = eluf(zi.x + zj.x)*av[0] + eluf(zi.y + zj.y)*av[1]
            + eluf(zi.z + zj.z)*av[2] + eluf(zi.w + zj.w)*av[3];
    p += __shfl_xor_sync(0xffffffffu, p, 1);
    p += __shfl_xor_sync(0xffffffffu, p, 2);
    if (sub == 0) {
        float a = softplusf(p) + 1e-6f;
        g_ae[(size_t)e * HH + head] = a;
        atomicAdd(&g_deg[(size_t)c * HH + head], a);
    }
}

// ---------------- dinv = deg^-1/2 -------------------------------------------------
__global__ void dinv_kernel()
{
    int i = blockIdx.x * blockDim.x + threadIdx.x;
    if (i < NN * HH) {
        float d = g_deg[i];
        g_dinv[i] = d > 0.f ? rsqrtf(d) : 0.f;
    }
}

// ---------------- propagate: h_new[col] += (dinv_r * a * dinv_c) * h_prev[row] ----
__global__ void prop_kernel(const int* __restrict__ ei, int flip)
{
    const float* hprev = flip ? g_hA : g_hB;   // flip=1: prev A -> new B
    float* hnew        = flip ? g_hB : g_hA;
    int e = (blockIdx.x * blockDim.x + threadIdx.x) >> 5;
    int lane = threadIdx.x & 31;
    if (e >= EPD) return;
    int r, c;
    if (e < EE) { r = ei[e]; c = ei[EE + e]; }
    else        { r = c = e - EE; }
    int head = lane >> 2;
    float a = g_ae[(size_t)e * HH + head]
            * g_dinv[(size_t)r * HH + head]
            * g_dinv[(size_t)c * HH + head];
    float4 h4 = *(const float4*)&hprev[(size_t)r * HC + (lane << 2)];
    float* dst = &hnew[(size_t)c * HC + (lane << 2)];
    asm volatile("red.global.add.v4.f32 [%0], {%1,%2,%3,%4};"
                 :: "l"(dst), "f"(a * h4.x), "f"(a * h4.y), "f"(a * h4.z), "f"(a * h4.w)
                 : "memory");
}

// ---------------- hop update: g from elu(concat(h_new, zs)); z += h*g; zs = z*decay
__global__ void hopupd_kernel(const float* __restrict__ hop_atts_k,
                              const float* __restrict__ hop_bias_k,
                              float decayk, int flip)
{
    const float* hnew = flip ? g_hB : g_hA;
    int w = (blockIdx.x * blockDim.x + threadIdx.x) >> 5;
    int lane = threadIdx.x & 31;
    if (w >= NN) return;
    int head = lane >> 2, sub = lane & 3;
    size_t off = (size_t)w * HC + (lane << 2);
    float4 h4  = *(const float4*)&hnew[off];
    float4 zs4 = *(const float4*)&g_zs[off];
    float4 z4  = *(const float4*)&g_z[off];
    const float* aw  = hop_atts_k + head * (2 * CC) + (sub << 2);
    const float* aw2 = aw + CC;
    float p = eluf(h4.x)*aw[0]  + eluf(h4.y)*aw[1]  + eluf(h4.z)*aw[2]  + eluf(h4.w)*aw[3]
            + eluf(zs4.x)*aw2[0] + eluf(zs4.y)*aw2[1] + eluf(zs4.z)*aw2[2] + eluf(zs4.w)*aw2[3];
    p += __shfl_xor_sync(0xffffffffu, p, 1);
    p += __shfl_xor_sync(0xffffffffu, p, 2);
    float g = p + hop_bias_k[head];
    z4.x = fmaf(h4.x, g, z4.x);
    z4.y = fmaf(h4.y, g, z4.y);
    z4.z = fmaf(h4.z, g, z4.z);
    z4.w = fmaf(h4.w, g, z4.w);
    *(float4*)&g_z[off] = z4;
    float4 zsn = make_float4(z4.x*decayk, z4.y*decayk, z4.z*decayk, z4.w*decayk);
    *(float4*)&g_zs[off] = zsn;
}

// ---------------- output: out = elu(z) @ Wout + bout  (N x 40) --------------------
__global__ void out_kernel(const float* __restrict__ Wout,
                           const float* __restrict__ bout,
                           float* __restrict__ out)
{
    __shared__ float Ws[HC * 40];
    __shared__ float bs[40];
    __shared__ float zsm[8][HC];
    int tid = threadIdx.x;
    for (int i = tid; i < HC * 40; i += 320) Ws[i] = Wout[i];
    if (tid < 40) bs[tid] = bout[tid];
    int nbase = blockIdx.x * 8;
    for (int i = tid; i < 8 * HC; i += 320) {
        int ln = i >> 7, c = i & 127;
        int gn = nbase + ln;
        float v = (gn < NN) ? g_z[(size_t)gn * HC + c] : 0.f;
        zsm[ln][c] = eluf(v);
    }
    __syncthreads();
    int ln = tid / 40, o = tid % 40;
    if (ln < 8) {
        int gn = nbase + ln;
        if (gn < NN) {
            float acc = bs[o];
            #pragma unroll 8
            for (int c = 0; c < HC; c++) acc = fmaf(zsm[ln][c], Ws[c * 40 + o], acc);
            out[(size_t)gn * 40 + o] = acc;
        }
    }
}

// ---------------- host orchestration ----------------------------------------------
extern "C" void kernel_launch(void* const* d_in, const int* in_sizes, int n_in,
                              void* d_out, int out_size)
{
    const float* x          = (const float*)d_in[0];
    const int*   ei         = (const int*)d_in[1];
    const float* W0         = (const float*)d_in[2];
    const float* b0         = (const float*)d_in[3];
    const float* W1         = (const float*)d_in[4];
    const float* b1         = (const float*)d_in[5];
    const float* Wout       = (const float*)d_in[6];
    const float* bout       = (const float*)d_in[7];
    const float* hop_att0   = (const float*)d_in[8];
    const float* hop_atts   = (const float*)d_in[9];
    const float* atts       = (const float*)d_in[10];
    const float* hop_biases = (const float*)d_in[11];
    float* out = (float*)d_out;

    float decay[5];
    for (int k = 0; k <= 4; k++) decay[k] = (float)log(1.0 / (k + 1) + 1.0 + 1e-6);

    const int GEMM_GRID = (NN + 63) / 64;
    const int NODE_GRID = (NN + 7) / 8;          // warp per node, 8 warps/block
    const int EDGE_GRID = (EPD + 7) / 8;         // warp per edge, 8 warps/block

    // MLP
    gemm_k<256, true,  0, 0><<<GEMM_GRID, 256>>>(x, W0, b0);         // g_h1 = elu(x@W0+b0)
    gemm_k<128, false, 1, 1><<<GEMM_GRID, 256>>>(nullptr, W1, b1);   // g_hA = g_h1@W1+b1

    // hop 0
    hop0_kernel<<<NODE_GRID, 256>>>(hop_att0, hop_biases, decay[0]);

    // hops 1..4  (flip=1: prev=A new=B; alternates)
    for (int k = 1; k <= 4; k++) {
        int flip = (k & 1);
        zero_kernel<<<4096, 256>>>(flip);
        edge_att_kernel<<<EDGE_GRID, 256>>>(ei, atts + (size_t)(k - 1) * HH * CC);
        dinv_kernel<<<(NN * HH + 255) / 256, 256>>>();
        prop_kernel<<<EDGE_GRID, 256>>>(ei, flip);
        hopupd_kernel<<<NODE_GRID, 256>>>(hop_atts + (size_t)(k - 1) * HH * 2 * CC,
                                          hop_biases + (size_t)k * HH,
                                          decay[k], flip);
    }

    // classifier
    out_kernel<<<(NN + 7) / 8, 320>>>(Wout, bout, out);
}